// round 14
// baseline (speedup 1.0000x reference)
#include <cuda_runtime.h>
#include <cuda_fp16.h>
#include <cstdint>

#define BATCH 8
#define SEQ   2048
#define DIM   1024
#define NST   256
#define HID   512
#define NEXP  8
#define NTOK  (BATCH*SEQ)   // 16384

// ---------------- device scratch (static, allocation-free) ----------------
__device__ __half g_xg[NTOK*DIM];                // x gathered to expert-compact order, fp16
__device__ __half g_Winh [NEXP*NST*DIM];
__device__ __half g_Wsinh[NEXP*HID*DIM];
__device__ __half g_Wsoh [NEXP*4*NST*HID];
__device__ __half g_Woth [NEXP*DIM*NST];
__device__ __half g_shh[NTOK*HID];               // silu out, fp16, compact
__device__ __half g_yh [NTOK*NST];               // scan out, fp16, compact
__device__ float g_u [NTOK*NST];
__device__ float g_a [NTOK*NST], g_bu[NTOK*NST], g_c[NTOK*NST], g_sk[NTOK*NST];
__device__ int g_list[NTOK];
__device__ int g_tileCnt[64][NEXP];
__device__ int g_eBase[NEXP];
__device__ int g_cnt[NEXP];
__device__ int g_beOff[BATCH][NEXP];
__device__ int g_beCnt[BATCH][NEXP];

__device__ __forceinline__ float sigmoidf_(float x){ return 1.f/(1.f+__expf(-x)); }

__device__ __forceinline__ uint32_t smem_u32(const void* p){
    uint32_t a;
    asm("{ .reg .u64 t; cvta.to.shared.u64 t, %1; cvt.u32.u64 %0, t; }" : "=r"(a) : "l"(p));
    return a;
}
__device__ __forceinline__ void ldsm_x4(uint32_t* r, uint32_t addr){
    asm volatile("ldmatrix.sync.aligned.m8n8.x4.shared.b16 {%0,%1,%2,%3}, [%4];"
        : "=r"(r[0]),"=r"(r[1]),"=r"(r[2]),"=r"(r[3]) : "r"(addr));
}
__device__ __forceinline__ void mma16816h(float* d, const uint32_t* a, uint32_t b0, uint32_t b1){
    asm volatile("mma.sync.aligned.m16n8k16.row.col.f32.f16.f16.f32 "
        "{%0,%1,%2,%3}, {%4,%5,%6,%7}, {%8,%9}, {%0,%1,%2,%3};"
        : "+f"(d[0]),"+f"(d[1]),"+f"(d[2]),"+f"(d[3])
        : "r"(a[0]),"r"(a[1]),"r"(a[2]),"r"(a[3]), "r"(b0),"r"(b1));
}
__device__ __forceinline__ void cpa16(uint32_t dst, const void* src){
    asm volatile("cp.async.cg.shared.global [%0], [%1], 16;" :: "r"(dst), "l"(src));
}
#define CP_COMMIT() asm volatile("cp.async.commit_group;" ::: "memory")
#define CP_WAIT1()  asm volatile("cp.async.wait_group 1;"  ::: "memory")
__device__ __forceinline__ uint32_t h2bits(__half2 h){ return *reinterpret_cast<uint32_t*>(&h); }
__device__ __forceinline__ int route_of(int tokid){
    unsigned x = (unsigned)tokid;
    x ^= x >> 16; x *= 2246822507u;
    x ^= x >> 13; x *= 3266489909u;
    x ^= x >> 16;
    return (int)(x & 7u);
}

// ---------------- fused kernel 0: count (blocks 0..63) + weight cvt -------
#define W0Q (NEXP*NST*DIM/4)
#define W1Q (NEXP*HID*DIM/4)
#define W2Q (NEXP*4*NST*HID/4)
#define W3Q (NEXP*DIM*NST/4)
#define WTOTQ (W0Q+W1Q+W2Q+W3Q)         // 3145728 quads
#define WPAIRS (WTOTQ/2)
#define CVT_BLKS (WPAIRS/256)           // 6144
__global__ void __launch_bounds__(256)
k0_count_cvtw(const int* __restrict__ tok,
              const float* __restrict__ s0, const float* __restrict__ s1,
              const float* __restrict__ s2, const float* __restrict__ s3)
{
    const int blk = blockIdx.x;
    if (blk < 64){
        int tid = threadIdx.x, wid = tid>>5, lane = tid&31;
        int r = route_of(tok[blk*256 + tid]);
        __shared__ int wcnt[8][8];
        unsigned m[8];
        #pragma unroll
        for (int e = 0; e < 8; e++) m[e] = __ballot_sync(0xffffffffu, r == e);
        if (lane < 8) wcnt[wid][lane] = __popc(m[lane]);
        __syncthreads();
        if (tid < 8){
            int s = 0;
            #pragma unroll
            for (int w = 0; w < 8; w++) s += wcnt[w][tid];
            g_tileCnt[blk][tid] = s;
        }
        return;
    }
    int p = (blk - 64)*256 + threadIdx.x;
    int j = p * 2;
    const float* src; __half* dst;
    if (j < W0Q){ src = s0; dst = g_Winh; }
    else if ((j -= W0Q) < W1Q){ src = s1; dst = g_Wsinh; }
    else if ((j -= W1Q) < W2Q){ src = s2; dst = g_Wsoh; }
    else { j -= W2Q; src = s3; dst = g_Woth; }
    #pragma unroll
    for (int q = 0; q < 2; q++){
        float4 v = reinterpret_cast<const float4*>(src)[j + q];
        reinterpret_cast<uint2*>(dst)[j + q] =
            make_uint2(h2bits(__floats2half2_rn(v.x, v.y)), h2bits(__floats2half2_rn(v.z, v.w)));
    }
}

// ---------------- kernel 1: place (each block recomputes prefix) ----------
__global__ void __launch_bounds__(256)
k1_place(const int* __restrict__ tok)
{
    const int blk = blockIdx.x, tid = threadIdx.x, wid = tid>>5, lane = tid&31;
    __shared__ int s_off[8];
    __shared__ int s_tot[8];
    __shared__ int s_base[8];
    __shared__ int wcnt[8][8];

    if (tid < 8){
        const int e = tid;
        int run = 0, off = 0;
        for (int t = 0; t < 64; t++){
            if (t == blk) off = run;
            run += g_tileCnt[t][e];
        }
        s_tot[e] = run;
        s_off[e] = off;
    }
    __syncthreads();
    if (tid < 8){
        int base = 0;
        for (int e = 0; e < tid; e++) base += s_tot[e];
        s_base[tid] = base;
        if (blk == 0){
            g_eBase[tid] = base;
            g_cnt[tid]   = s_tot[tid];
            for (int b = 0; b < 8; b++){
                int run = 0, off = 0, s = 0;
                for (int t = 0; t < 64; t++){
                    if (t == b*8) off = run;
                    run += g_tileCnt[t][tid];
                    if (t >= b*8 && t < b*8 + 8) s += g_tileCnt[t][tid];
                }
                g_beOff[b][tid] = base + off;
                g_beCnt[b][tid] = s;
            }
        }
    }

    const int t = blk*256 + tid;
    const int r = route_of(tok[t]);
    unsigned m[8];
    #pragma unroll
    for (int e = 0; e < 8; e++) m[e] = __ballot_sync(0xffffffffu, r == e);
    if (lane < 8) wcnt[wid][lane] = __popc(m[lane]);
    __syncthreads();
    int wbase = 0;
    for (int w = 0; w < wid; w++) wbase += wcnt[w][r];
    int rank = wbase + __popc(m[r] & ((1u << lane) - 1u));
    g_list[s_base[r] + s_off[r] + rank] = t;
}

// ---------------- kernel 2: x gather + fp16 round --------------------------
__global__ void __launch_bounds__(256)
cvt_x(const float* __restrict__ x){
    const int pos = blockIdx.x;
    const int i   = threadIdx.x;
    const int tok = g_list[pos];
    float4 v = reinterpret_cast<const float4*>(x)[(size_t)tok*256 + i];
    reinterpret_cast<uint2*>(g_xg)[(size_t)pos*256 + i] =
        make_uint2(h2bits(__floats2half2_rn(v.x, v.y)), h2bits(__floats2half2_rn(v.z, v.w)));
}

// ---------------- grouped GEMM: persistent tiles, frozen mainloop ---------
// C = A . W^T ; A compact fp16 (pre-gathered), W fp16.
// 296 persistent CTAs loop over tile space (m fastest -> L2 B-sharing).
// MODE 0: fused u|sh (NB=6: n0<256 -> Win/u, else Wsin/silu->sh), K=1024
// MODE 2: gates (NB=8, Wsout), K=512.   MODE 3: out proj (NB=8, Wout), K=256
#define SSTR   144
#define ATILE  (128*SSTR)         // 18432
#define STAGE  (2*ATILE)          // 36864 : A | B
#define GSMEM  (3*STAGE)          // 110592
#define MB     20                 // m-block capacity per expert
#define NSM_CTAS 296

template<int MODE, int NB>
__global__ void __launch_bounds__(256, 2)
gemm_mma(const __half* __restrict__ A,
         const __half* __restrict__ W0, const __half* __restrict__ W1,
         const float* __restrict__ dparam, float* __restrict__ outp, int K)
{
    extern __shared__ __align__(16) char sm[];
    const int tid  = threadIdx.x;
    const int wid  = tid >> 5;
    const int lane = tid & 31;
    const int NC   = K >> 6;

    const uint32_t sb = smem_u32(sm);
    const int lrow = tid >> 1;
    const int lcol = (tid & 1) * 32;
    const uint32_t aoff = sb + (uint32_t)(lrow*SSTR + lcol*2);
    const uint32_t boff = aoff + ATILE;
    const int wm = wid & 1, wn = wid >> 1;
    const uint32_t a_base = sb + (uint32_t)((wm*64 + (lane & 15))*SSTR + (lane >> 4)*16);
    const uint32_t b_base = sb + ATILE +
        (uint32_t)((wn*32 + (lane >> 4)*8 + (lane & 7))*SSTR + ((lane >> 3) & 1)*16);

    const int NT = MB * NB * NEXP;
    for (int t = blockIdx.x; t < NT; t += NSM_CTAS){
        const int e    = t / (MB * NB);
        const int rem  = t - e * (MB * NB);
        const int m0   = (rem % MB) * 128;
        const int n0   = (rem / MB) * 128;
        const int cnt  = g_cnt[e];
        if (m0 >= cnt) continue;
        const int posBase = g_eBase[e];

        const __half* W;
        int nloc;
        if (MODE == 0){
            if (n0 < 256){ W = W0 + (size_t)e * NST * K;  nloc = n0; }
            else         { W = W1 + (size_t)e * HID * K;  nloc = n0 - 256; }
        } else {
            W = W0 + (size_t)e * 1024 * K;  nloc = n0;
        }

        int am = m0 + lrow; if (am >= cnt) am = cnt - 1;
        const __half* ap = A + (size_t)(posBase + am)*K + lcol;
        const __half* bp = W + (size_t)(nloc + lrow)*K + lcol;

        float acc[4][4][4];
        #pragma unroll
        for (int mi=0;mi<4;mi++)
            #pragma unroll
            for (int ni=0;ni<4;ni++)
                #pragma unroll
                for (int q=0;q<4;q++) acc[mi][ni][q]=0.f;

        // smem reuse safety across tiles: previous tile's compute must be done
        __syncthreads();

        // prologue
        {
            #pragma unroll
            for (int q = 0; q < 4; q++){
                cpa16(aoff + q*16, ap + q*8);
                cpa16(boff + q*16, bp + q*8);
            }
            CP_COMMIT();
            #pragma unroll
            for (int q = 0; q < 4; q++){
                cpa16(aoff + STAGE + q*16, ap + 64 + q*8);
                cpa16(boff + STAGE + q*16, bp + 64 + q*8);
            }
            CP_COMMIT();
        }

        for (int c = 0; c < NC; c++){
            CP_WAIT1();
            __syncthreads();
            if (c + 2 < NC){
                const uint32_t st = (uint32_t)(((c + 2) % 3) * STAGE);
                const int k0 = (c + 2) << 6;
                #pragma unroll
                for (int q = 0; q < 4; q++){
                    cpa16(aoff + st + q*16, ap + k0 + q*8);
                    cpa16(boff + st + q*16, bp + k0 + q*8);
                }
            }
            CP_COMMIT();

            const uint32_t ab = a_base + (c % 3)*STAGE;
            const uint32_t bb = b_base + (c % 3)*STAGE;
            #pragma unroll
            for (int ks = 0; ks < 4; ks++){
                uint32_t ah[4][4], bh[2][4];
                #pragma unroll
                for (int mi = 0; mi < 4; mi++)
                    ldsm_x4(ah[mi], ab + mi*16*SSTR + ks*32);
                #pragma unroll
                for (int np = 0; np < 2; np++)
                    ldsm_x4(bh[np], bb + np*16*SSTR + ks*32);
                #pragma unroll
                for (int mi = 0; mi < 4; mi++)
                    #pragma unroll
                    for (int ni = 0; ni < 4; ni++){
                        const int np = ni >> 1, h = (ni & 1)*2;
                        mma16816h(acc[mi][ni], ah[mi], bh[np][h], bh[np][h+1]);
                    }
            }
        }

        // ---- epilogue (frozen layout)
        const int sec = (MODE == 2) ? (n0 >> 8) : 0;
        #pragma unroll
        for (int mi = 0; mi < 4; mi++){
            const int rt0 = wm*64 + mi*16 + (lane >> 2);
            #pragma unroll
            for (int hf = 0; hf < 2; hf++){
                const int rt = rt0 + hf*8;
                const int m  = m0 + rt;
                if (m >= cnt) continue;
                const int pos = posBase + m;
                #pragma unroll
                for (int ni = 0; ni < 4; ni++){
                    float v0 = acc[mi][ni][hf*2], v1 = acc[mi][ni][hf*2+1];
                    const int col = n0 + wn*32 + (ni>>1)*16 + (ni&1)*8 + (lane&3)*2;
                    if (MODE == 0){
                        if (col < 256){
                            *(float2*)(g_u + (size_t)pos*NST + col) = make_float2(v0, v1);
                        } else {
                            float s0 = v0*sigmoidf_(v0), s1 = v1*sigmoidf_(v1);
                            *reinterpret_cast<uint32_t*>(g_shh + (size_t)pos*HID + (col - 256)) =
                                h2bits(__floats2half2_rn(s0, s1));
                        }
                    } else if (MODE == 2){
                        const int off = col & 255;
                        const size_t base = (size_t)pos*NST + off;
                        if (sec == 0){
                            *(float2*)(g_a + base) = make_float2(sigmoidf_(v0), sigmoidf_(v1));
                        } else if (sec == 1){
                            float2 u2 = *(const float2*)(g_u + base);
                            *(float2*)(g_bu + base) = make_float2(tanhf(v0)*u2.x, tanhf(v1)*u2.y);
                        } else if (sec == 2){
                            *(float2*)(g_c + base) = make_float2(tanhf(v0), tanhf(v1));
                        } else {
                            float2 u2 = *(const float2*)(g_u + base);
                            float2 d2 = *(const float2*)(dparam + e*NST + off);
                            *(float2*)(g_sk + base) =
                                make_float2(sigmoidf_(v0)*d2.x*u2.x, sigmoidf_(v1)*d2.y*u2.y);
                        }
                    } else {
                        const int tok = g_list[pos];
                        *(float2*)(outp + (size_t)tok*DIM + col) = make_float2(v0, v1);
                    }
                }
            }
        }
    }
}

// ---------------- sequential scan, compact streaming, fp16 y (frozen) -----
__global__ void __launch_bounds__(256)
scan_kernel()
{
    const int b = blockIdx.x, e = blockIdx.y, tid = threadIdx.x;
    const int pos0 = g_beOff[b][e];
    const int n    = g_beCnt[b][e];

    float a[2][4], bu[2][4], cc[2][4], sk[2][4];
    #pragma unroll
    for (int j = 0; j < 4; j++){
        bool v = j < n;
        size_t idx = ((size_t)(pos0 + (v ? j : 0)))*NST + tid;
        a [0][j] = v ? g_a [idx] : 0.f;
        bu[0][j] = v ? g_bu[idx] : 0.f;
        cc[0][j] = v ? g_c [idx] : 0.f;
        sk[0][j] = v ? g_sk[idx] : 0.f;
    }

    float h = 0.f;
    int cur = 0;
    for (int base = 0; base < n; base += 4){
        const int nxt = cur ^ 1;
        #pragma unroll
        for (int j = 0; j < 4; j++){
            int i = base + 4 + j;
            if (i < n){
                size_t idx = ((size_t)(pos0 + i))*NST + tid;
                a [nxt][j] = g_a [idx];
                bu[nxt][j] = g_bu[idx];
                cc[nxt][j] = g_c [idx];
                sk[nxt][j] = g_sk[idx];
            }
        }
        #pragma unroll
        for (int j = 0; j < 4; j++){
            int i = base + j;
            if (i < n){
                h = fmaf(a[cur][j], h, bu[cur][j]);
                float y = fmaf(cc[cur][j], h, sk[cur][j]);
                g_yh[((size_t)(pos0 + i))*NST + tid] = __float2half(y);
            }
        }
        cur = nxt;
    }
}

// ---------------- launch ----------------
extern "C" void kernel_launch(void* const* d_in, const int* in_sizes, int n_in,
                              void* d_out, int out_size)
{
    const float* x     = (const float*)d_in[0];
    const int*   tok   = (const int*)  d_in[1];
    const float* Win   = (const float*)d_in[2];
    const float* Wsin  = (const float*)d_in[3];
    const float* Wsout = (const float*)d_in[4];
    const float* Wout  = (const float*)d_in[5];
    const float* dpar  = (const float*)d_in[6];
    float* outp = (float*)d_out;
    (void)in_sizes; (void)n_in; (void)out_size;

    cudaFuncSetAttribute(gemm_mma<0,6>, cudaFuncAttributeMaxDynamicSharedMemorySize, GSMEM);
    cudaFuncSetAttribute(gemm_mma<2,8>, cudaFuncAttributeMaxDynamicSharedMemorySize, GSMEM);
    cudaFuncSetAttribute(gemm_mma<3,8>, cudaFuncAttributeMaxDynamicSharedMemorySize, GSMEM);

    __half *xg, *shh, *yh, *winh, *wsih, *wsoh, *woth;
    cudaGetSymbolAddress((void**)&xg,   g_xg);
    cudaGetSymbolAddress((void**)&shh,  g_shh);
    cudaGetSymbolAddress((void**)&yh,   g_yh);
    cudaGetSymbolAddress((void**)&winh, g_Winh);
    cudaGetSymbolAddress((void**)&wsih, g_Wsinh);
    cudaGetSymbolAddress((void**)&wsoh, g_Wsoh);
    cudaGetSymbolAddress((void**)&woth, g_Woth);

    k0_count_cvtw<<<64 + CVT_BLKS, 256>>>(tok, Win, Wsin, Wsout, Wout);
    k1_place<<<64, 256>>>(tok);
    cvt_x<<<NTOK, 256>>>(x);

    dim3 blk(256);
    // fused u|sh GEMM, K=1024, persistent
    gemm_mma<0,6><<<NSM_CTAS, blk, GSMEM>>>(xg,  winh, wsih, nullptr, nullptr, DIM);
    // gates = sh . Wsout^T (K=512), persistent
    gemm_mma<2,8><<<NSM_CTAS, blk, GSMEM>>>(shh, wsoh, nullptr, dpar,  nullptr, HID);
    // recurrence
    scan_kernel<<<dim3(BATCH, NEXP), 256>>>();
    // out = y . Wout^T (K=256), persistent
    gemm_mma<3,8><<<NSM_CTAS, blk, GSMEM>>>(yh,  woth, nullptr, nullptr, outp,  NST);
}

// round 15
// speedup vs baseline: 1.1125x; 1.1125x over previous
#include <cuda_runtime.h>
#include <cuda_fp16.h>
#include <cstdint>

#define BATCH 8
#define SEQ   2048
#define DIM   1024
#define NST   256
#define HID   512
#define NEXP  8
#define NTOK  (BATCH*SEQ)   // 16384

// ---------------- device scratch (static, allocation-free) ----------------
__device__ __half g_xg[NTOK*DIM];                // x gathered to expert-compact order, fp16
__device__ __half g_Winh [NEXP*NST*DIM];
__device__ __half g_Wsinh[NEXP*HID*DIM];
__device__ __half g_Wsoh [NEXP*4*NST*HID];
__device__ __half g_Woth [NEXP*DIM*NST];
__device__ __half g_shh[NTOK*HID];               // silu out, fp16, compact
__device__ __half g_yh [NTOK*NST];               // scan out, fp16, compact
__device__ float g_u [NTOK*NST];
__device__ float g_a [NTOK*NST], g_bu[NTOK*NST], g_c[NTOK*NST], g_sk[NTOK*NST];
__device__ int g_list[NTOK];
__device__ int g_tileCnt[64][NEXP];
__device__ int g_eBase[NEXP];
__device__ int g_cnt[NEXP];
__device__ int g_beOff[BATCH][NEXP];
__device__ int g_beCnt[BATCH][NEXP];

__device__ __forceinline__ float sigmoidf_(float x){ return 1.f/(1.f+__expf(-x)); }
// fast tanh: 1 - 2/(e^{2x}+1); |err| ~1e-6, safe at extremes (inf -> 1, 0 -> -1)
__device__ __forceinline__ float ftanh_(float x){
    float e = __expf(2.f*x);
    return 1.f - __fdividef(2.f, e + 1.f);
}

__device__ __forceinline__ uint32_t smem_u32(const void* p){
    uint32_t a;
    asm("{ .reg .u64 t; cvta.to.shared.u64 t, %1; cvt.u32.u64 %0, t; }" : "=r"(a) : "l"(p));
    return a;
}
__device__ __forceinline__ void ldsm_x4(uint32_t* r, uint32_t addr){
    asm volatile("ldmatrix.sync.aligned.m8n8.x4.shared.b16 {%0,%1,%2,%3}, [%4];"
        : "=r"(r[0]),"=r"(r[1]),"=r"(r[2]),"=r"(r[3]) : "r"(addr));
}
__device__ __forceinline__ void mma16816h(float* d, const uint32_t* a, uint32_t b0, uint32_t b1){
    asm volatile("mma.sync.aligned.m16n8k16.row.col.f32.f16.f16.f32 "
        "{%0,%1,%2,%3}, {%4,%5,%6,%7}, {%8,%9}, {%0,%1,%2,%3};"
        : "+f"(d[0]),"+f"(d[1]),"+f"(d[2]),"+f"(d[3])
        : "r"(a[0]),"r"(a[1]),"r"(a[2]),"r"(a[3]), "r"(b0),"r"(b1));
}
__device__ __forceinline__ void cpa16(uint32_t dst, const void* src){
    asm volatile("cp.async.cg.shared.global [%0], [%1], 16;" :: "r"(dst), "l"(src));
}
#define CP_COMMIT() asm volatile("cp.async.commit_group;" ::: "memory")
#define CP_WAIT1()  asm volatile("cp.async.wait_group 1;"  ::: "memory")
__device__ __forceinline__ uint32_t h2bits(__half2 h){ return *reinterpret_cast<uint32_t*>(&h); }
__device__ __forceinline__ int route_of(int tokid){
    unsigned x = (unsigned)tokid;
    x ^= x >> 16; x *= 2246822507u;
    x ^= x >> 13; x *= 3266489909u;
    x ^= x >> 16;
    return (int)(x & 7u);
}

// ---------------- fused kernel 0: count (blocks 0..63) + weight cvt -------
#define W0Q (NEXP*NST*DIM/4)
#define W1Q (NEXP*HID*DIM/4)
#define W2Q (NEXP*4*NST*HID/4)
#define W3Q (NEXP*DIM*NST/4)
#define WTOTQ (W0Q+W1Q+W2Q+W3Q)
#define WPAIRS (WTOTQ/2)
#define CVT_BLKS (WPAIRS/256)           // 6144
__global__ void __launch_bounds__(256)
k0_count_cvtw(const int* __restrict__ tok,
              const float* __restrict__ s0, const float* __restrict__ s1,
              const float* __restrict__ s2, const float* __restrict__ s3)
{
    const int blk = blockIdx.x;
    if (blk < 64){
        int tid = threadIdx.x, wid = tid>>5, lane = tid&31;
        int r = route_of(tok[blk*256 + tid]);
        __shared__ int wcnt[8][8];
        unsigned m[8];
        #pragma unroll
        for (int e = 0; e < 8; e++) m[e] = __ballot_sync(0xffffffffu, r == e);
        if (lane < 8) wcnt[wid][lane] = __popc(m[lane]);
        __syncthreads();
        if (tid < 8){
            int s = 0;
            #pragma unroll
            for (int w = 0; w < 8; w++) s += wcnt[w][tid];
            g_tileCnt[blk][tid] = s;
        }
        return;
    }
    int p = (blk - 64)*256 + threadIdx.x;
    int j = p * 2;
    const float* src; __half* dst;
    if (j < W0Q){ src = s0; dst = g_Winh; }
    else if ((j -= W0Q) < W1Q){ src = s1; dst = g_Wsinh; }
    else if ((j -= W1Q) < W2Q){ src = s2; dst = g_Wsoh; }
    else { j -= W2Q; src = s3; dst = g_Woth; }
    #pragma unroll
    for (int q = 0; q < 2; q++){
        float4 v = reinterpret_cast<const float4*>(src)[j + q];
        reinterpret_cast<uint2*>(dst)[j + q] =
            make_uint2(h2bits(__floats2half2_rn(v.x, v.y)), h2bits(__floats2half2_rn(v.z, v.w)));
    }
}

// ---------------- kernel 1: place (each block recomputes prefix) ----------
__global__ void __launch_bounds__(256)
k1_place(const int* __restrict__ tok)
{
    const int blk = blockIdx.x, tid = threadIdx.x, wid = tid>>5, lane = tid&31;
    __shared__ int s_off[8];
    __shared__ int s_tot[8];
    __shared__ int s_base[8];
    __shared__ int wcnt[8][8];

    if (tid < 8){
        const int e = tid;
        int run = 0, off = 0;
        for (int t = 0; t < 64; t++){
            if (t == blk) off = run;
            run += g_tileCnt[t][e];
        }
        s_tot[e] = run;
        s_off[e] = off;
    }
    __syncthreads();
    if (tid < 8){
        int base = 0;
        for (int e = 0; e < tid; e++) base += s_tot[e];
        s_base[tid] = base;
        if (blk == 0){
            g_eBase[tid] = base;
            g_cnt[tid]   = s_tot[tid];
            for (int b = 0; b < 8; b++){
                int run = 0, off = 0, s = 0;
                for (int t = 0; t < 64; t++){
                    if (t == b*8) off = run;
                    run += g_tileCnt[t][tid];
                    if (t >= b*8 && t < b*8 + 8) s += g_tileCnt[t][tid];
                }
                g_beOff[b][tid] = base + off;
                g_beCnt[b][tid] = s;
            }
        }
    }

    const int t = blk*256 + tid;
    const int r = route_of(tok[t]);
    unsigned m[8];
    #pragma unroll
    for (int e = 0; e < 8; e++) m[e] = __ballot_sync(0xffffffffu, r == e);
    if (lane < 8) wcnt[wid][lane] = __popc(m[lane]);
    __syncthreads();
    int wbase = 0;
    for (int w = 0; w < wid; w++) wbase += wcnt[w][r];
    int rank = wbase + __popc(m[r] & ((1u << lane) - 1u));
    g_list[s_base[r] + s_off[r] + rank] = t;
}

// ---------------- kernel 2: x gather + fp16 round --------------------------
__global__ void __launch_bounds__(256)
cvt_x(const float* __restrict__ x){
    const int pos = blockIdx.x;
    const int i   = threadIdx.x;
    const int tok = g_list[pos];
    float4 v = reinterpret_cast<const float4*>(x)[(size_t)tok*256 + i];
    reinterpret_cast<uint2*>(g_xg)[(size_t)pos*256 + i] =
        make_uint2(h2bits(__floats2half2_rn(v.x, v.y)), h2bits(__floats2half2_rn(v.z, v.w)));
}

// ---------------- grouped GEMM: 128x128 tile, 3-stage cp.async (frozen r13)
#define SSTR   144
#define ATILE  (128*SSTR)         // 18432
#define STAGE  (2*ATILE)          // 36864 : A | B
#define GSMEM  (3*STAGE)          // 110592

template<int MODE>
__global__ void __launch_bounds__(256, 2)
gemm_mma(const __half* __restrict__ A,
         const __half* __restrict__ W0, const __half* __restrict__ W1,
         const float* __restrict__ dparam, float* __restrict__ outp, int K)
{
    const int e   = blockIdx.z;
    const int cnt = g_cnt[e];
    const int m0  = blockIdx.x * 128;
    if (m0 >= cnt) return;
    const int n0  = blockIdx.y * 128;
    const int posBase = g_eBase[e];

    const __half* W;
    int nloc;
    if (MODE == 0){
        if (n0 < 256){ W = W0 + (size_t)e * NST * K;   nloc = n0; }
        else         { W = W1 + (size_t)e * HID * K;   nloc = n0 - 256; }
    } else {
        W = W0 + (size_t)e * 1024 * K;  nloc = n0;
    }

    extern __shared__ __align__(16) char sm[];

    const int tid  = threadIdx.x;
    const int wid  = tid >> 5;
    const int lane = tid & 31;

    const int lrow = tid >> 1;
    const int lcol = (tid & 1) * 32;
    int am = m0 + lrow; if (am >= cnt) am = cnt - 1;
    const __half* ap = A + (size_t)(posBase + am)*K + lcol;
    const __half* bp = W + (size_t)(nloc + lrow)*K + lcol;
    const uint32_t sb = smem_u32(sm);
    const uint32_t aoff = sb + (uint32_t)(lrow*SSTR + lcol*2);
    const uint32_t boff = aoff + ATILE;

    const int wm = wid & 1, wn = wid >> 1;
    const uint32_t a_base = sb + (uint32_t)((wm*64 + (lane & 15))*SSTR + (lane >> 4)*16);
    const uint32_t b_base = sb + ATILE +
        (uint32_t)((wn*32 + (lane >> 4)*8 + (lane & 7))*SSTR + ((lane >> 3) & 1)*16);

    float acc[4][4][4];
    #pragma unroll
    for (int mi=0;mi<4;mi++)
        #pragma unroll
        for (int ni=0;ni<4;ni++)
            #pragma unroll
            for (int q=0;q<4;q++) acc[mi][ni][q]=0.f;

    const int NC = K >> 6;

    auto issue = [&](int c){
        const uint32_t st = (uint32_t)((c % 3) * STAGE);
        const int k0 = c << 6;
        #pragma unroll
        for (int q = 0; q < 4; q++){
            cpa16(aoff + st + q*16, ap + k0 + q*8);
            cpa16(boff + st + q*16, bp + k0 + q*8);
        }
    };

    issue(0); CP_COMMIT();
    issue(1); CP_COMMIT();

    for (int c = 0; c < NC; c++){
        CP_WAIT1();
        __syncthreads();
        if (c + 2 < NC) issue(c + 2);
        CP_COMMIT();

        const uint32_t ab = a_base + (c % 3)*STAGE;
        const uint32_t bb = b_base + (c % 3)*STAGE;
        #pragma unroll
        for (int ks = 0; ks < 4; ks++){
            uint32_t ah[4][4], bh[2][4];
            #pragma unroll
            for (int mi = 0; mi < 4; mi++)
                ldsm_x4(ah[mi], ab + mi*16*SSTR + ks*32);
            #pragma unroll
            for (int np = 0; np < 2; np++)
                ldsm_x4(bh[np], bb + np*16*SSTR + ks*32);
            #pragma unroll
            for (int mi = 0; mi < 4; mi++)
                #pragma unroll
                for (int ni = 0; ni < 4; ni++){
                    const int np = ni >> 1, h = (ni & 1)*2;
                    mma16816h(acc[mi][ni], ah[mi], bh[np][h], bh[np][h+1]);
                }
        }
    }

    const int sec = (MODE == 2) ? (n0 >> 8) : 0;
    #pragma unroll
    for (int mi = 0; mi < 4; mi++){
        const int rt0 = wm*64 + mi*16 + (lane >> 2);
        #pragma unroll
        for (int hf = 0; hf < 2; hf++){
            const int rt = rt0 + hf*8;
            const int m  = m0 + rt;
            if (m >= cnt) continue;
            const int pos = posBase + m;
            #pragma unroll
            for (int ni = 0; ni < 4; ni++){
                float v0 = acc[mi][ni][hf*2], v1 = acc[mi][ni][hf*2+1];
                const int col = n0 + wn*32 + (ni>>1)*16 + (ni&1)*8 + (lane&3)*2;
                if (MODE == 0){
                    if (col < 256){
                        *(float2*)(g_u + (size_t)pos*NST + col) = make_float2(v0, v1);
                    } else {
                        float s0 = v0*sigmoidf_(v0), s1 = v1*sigmoidf_(v1);
                        *reinterpret_cast<uint32_t*>(g_shh + (size_t)pos*HID + (col - 256)) =
                            h2bits(__floats2half2_rn(s0, s1));
                    }
                } else if (MODE == 2){
                    const int off = col & 255;
                    const size_t base = (size_t)pos*NST + off;
                    if (sec == 0){
                        *(float2*)(g_a + base) = make_float2(sigmoidf_(v0), sigmoidf_(v1));
                    } else if (sec == 1){
                        float2 u2 = *(const float2*)(g_u + base);
                        *(float2*)(g_bu + base) = make_float2(ftanh_(v0)*u2.x, ftanh_(v1)*u2.y);
                    } else if (sec == 2){
                        *(float2*)(g_c + base) = make_float2(ftanh_(v0), ftanh_(v1));
                    } else {
                        float2 u2 = *(const float2*)(g_u + base);
                        float2 d2 = *(const float2*)(dparam + e*NST + off);
                        *(float2*)(g_sk + base) =
                            make_float2(sigmoidf_(v0)*d2.x*u2.x, sigmoidf_(v1)*d2.y*u2.y);
                    }
                } else {
                    const int tok = g_list[pos];
                    *(float2*)(outp + (size_t)tok*DIM + col) = make_float2(v0, v1);
                }
            }
        }
    }
}

// ---------------- sequential scan, compact streaming, 8-deep prefetch -----
__global__ void __launch_bounds__(256)
scan_kernel()
{
    const int b = blockIdx.x, e = blockIdx.y, tid = threadIdx.x;
    const int pos0 = g_beOff[b][e];
    const int n    = g_beCnt[b][e];

    float a[2][8], bu[2][8], cc[2][8], sk[2][8];
    #pragma unroll
    for (int j = 0; j < 8; j++){
        bool v = j < n;
        size_t idx = ((size_t)(pos0 + (v ? j : 0)))*NST + tid;
        a [0][j] = v ? g_a [idx] : 0.f;
        bu[0][j] = v ? g_bu[idx] : 0.f;
        cc[0][j] = v ? g_c [idx] : 0.f;
        sk[0][j] = v ? g_sk[idx] : 0.f;
    }

    float h = 0.f;
    int cur = 0;
    for (int base = 0; base < n; base += 8){
        const int nxt = cur ^ 1;
        #pragma unroll
        for (int j = 0; j < 8; j++){
            int i = base + 8 + j;
            if (i < n){
                size_t idx = ((size_t)(pos0 + i))*NST + tid;
                a [nxt][j] = g_a [idx];
                bu[nxt][j] = g_bu[idx];
                cc[nxt][j] = g_c [idx];
                sk[nxt][j] = g_sk[idx];
            }
        }
        #pragma unroll
        for (int j = 0; j < 8; j++){
            int i = base + j;
            if (i < n){
                h = fmaf(a[cur][j], h, bu[cur][j]);
                float y = fmaf(cc[cur][j], h, sk[cur][j]);
                g_yh[((size_t)(pos0 + i))*NST + tid] = __float2half(y);
            }
        }
        cur = nxt;
    }
}

// ---------------- launch ----------------
extern "C" void kernel_launch(void* const* d_in, const int* in_sizes, int n_in,
                              void* d_out, int out_size)
{
    const float* x     = (const float*)d_in[0];
    const int*   tok   = (const int*)  d_in[1];
    const float* Win   = (const float*)d_in[2];
    const float* Wsin  = (const float*)d_in[3];
    const float* Wsout = (const float*)d_in[4];
    const float* Wout  = (const float*)d_in[5];
    const float* dpar  = (const float*)d_in[6];
    float* outp = (float*)d_out;
    (void)in_sizes; (void)n_in; (void)out_size;

    cudaFuncSetAttribute(gemm_mma<0>, cudaFuncAttributeMaxDynamicSharedMemorySize, GSMEM);
    cudaFuncSetAttribute(gemm_mma<2>, cudaFuncAttributeMaxDynamicSharedMemorySize, GSMEM);
    cudaFuncSetAttribute(gemm_mma<3>, cudaFuncAttributeMaxDynamicSharedMemorySize, GSMEM);

    __half *xg, *shh, *yh, *winh, *wsih, *wsoh, *woth;
    cudaGetSymbolAddress((void**)&xg,   g_xg);
    cudaGetSymbolAddress((void**)&shh,  g_shh);
    cudaGetSymbolAddress((void**)&yh,   g_yh);
    cudaGetSymbolAddress((void**)&winh, g_Winh);
    cudaGetSymbolAddress((void**)&wsih, g_Wsinh);
    cudaGetSymbolAddress((void**)&wsoh, g_Wsoh);
    cudaGetSymbolAddress((void**)&woth, g_Woth);

    k0_count_cvtw<<<64 + CVT_BLKS, 256>>>(tok, Win, Wsin, Wsout, Wout);
    k1_place<<<64, 256>>>(tok);
    cvt_x<<<NTOK, 256>>>(x);

    dim3 blk(256);
    // fused u|sh GEMM, K=1024
    gemm_mma<0><<<dim3(20, 6, NEXP), blk, GSMEM>>>(xg,  winh, wsih, nullptr, nullptr, DIM);
    // gates = sh . Wsout^T (K=512)
    gemm_mma<2><<<dim3(20, 8, NEXP), blk, GSMEM>>>(shh, wsoh, nullptr, dpar,  nullptr, HID);
    // recurrence
    scan_kernel<<<dim3(BATCH, NEXP), 256>>>();
    // out = y . Wout^T (K=256)
    gemm_mma<3><<<dim3(20, 8, NEXP), blk, GSMEM>>>(yh,  woth, nullptr, nullptr, outp,  NST);
}

// round 16
// speedup vs baseline: 1.5765x; 1.4170x over previous
#include <cuda_runtime.h>
#include <cuda_fp16.h>
#include <cstdint>

#define BATCH 8
#define SEQ   2048
#define DIM   1024
#define NST   256
#define HID   512
#define NEXP  8
#define NTOK  (BATCH*SEQ)   // 16384
#define NSEG  8

// ---------------- device scratch (static, allocation-free) ----------------
__device__ __half g_xg[NTOK*DIM];
__device__ __half g_Winh [NEXP*NST*DIM];
__device__ __half g_Wsinh[NEXP*HID*DIM];
__device__ __half g_Wsoh [NEXP*4*NST*HID];
__device__ __half g_Woth [NEXP*DIM*NST];
__device__ __half g_shh[NTOK*HID];
__device__ __half g_yh [NTOK*NST];
__device__ float g_u [NTOK*NST];
__device__ float g_a [NTOK*NST], g_bu[NTOK*NST], g_c[NTOK*NST], g_sk[NTOK*NST];
__device__ float g_segP[BATCH*NEXP*NSEG*NST];
__device__ float g_segS[BATCH*NEXP*NSEG*NST];
__device__ int g_list[NTOK];
__device__ int g_tileCnt[64][NEXP];
__device__ int g_eBase[NEXP];
__device__ int g_cnt[NEXP];
__device__ int g_beOff[BATCH][NEXP];
__device__ int g_beCnt[BATCH][NEXP];

__device__ __forceinline__ float sigmoidf_(float x){ return 1.f/(1.f+__expf(-x)); }
__device__ __forceinline__ float ftanh_(float x){
    float e = __expf(2.f*x);
    return 1.f - __fdividef(2.f, e + 1.f);
}

__device__ __forceinline__ uint32_t smem_u32(const void* p){
    uint32_t a;
    asm("{ .reg .u64 t; cvta.to.shared.u64 t, %1; cvt.u32.u64 %0, t; }" : "=r"(a) : "l"(p));
    return a;
}
__device__ __forceinline__ void ldsm_x4(uint32_t* r, uint32_t addr){
    asm volatile("ldmatrix.sync.aligned.m8n8.x4.shared.b16 {%0,%1,%2,%3}, [%4];"
        : "=r"(r[0]),"=r"(r[1]),"=r"(r[2]),"=r"(r[3]) : "r"(addr));
}
__device__ __forceinline__ void mma16816h(float* d, const uint32_t* a, uint32_t b0, uint32_t b1){
    asm volatile("mma.sync.aligned.m16n8k16.row.col.f32.f16.f16.f32 "
        "{%0,%1,%2,%3}, {%4,%5,%6,%7}, {%8,%9}, {%0,%1,%2,%3};"
        : "+f"(d[0]),"+f"(d[1]),"+f"(d[2]),"+f"(d[3])
        : "r"(a[0]),"r"(a[1]),"r"(a[2]),"r"(a[3]), "r"(b0),"r"(b1));
}
__device__ __forceinline__ void cpa16(uint32_t dst, const void* src){
    asm volatile("cp.async.cg.shared.global [%0], [%1], 16;" :: "r"(dst), "l"(src));
}
#define CP_COMMIT() asm volatile("cp.async.commit_group;" ::: "memory")
#define CP_WAIT1()  asm volatile("cp.async.wait_group 1;"  ::: "memory")
__device__ __forceinline__ uint32_t h2bits(__half2 h){ return *reinterpret_cast<uint32_t*>(&h); }
__device__ __forceinline__ int route_of(int tokid){
    unsigned x = (unsigned)tokid;
    x ^= x >> 16; x *= 2246822507u;
    x ^= x >> 13; x *= 3266489909u;
    x ^= x >> 16;
    return (int)(x & 7u);
}

// ---------------- fused kernel 0: count (blocks 0..63) + weight cvt -------
#define W0Q (NEXP*NST*DIM/4)
#define W1Q (NEXP*HID*DIM/4)
#define W2Q (NEXP*4*NST*HID/4)
#define W3Q (NEXP*DIM*NST/4)
#define WTOTQ (W0Q+W1Q+W2Q+W3Q)
#define WPAIRS (WTOTQ/2)
#define CVT_BLKS (WPAIRS/256)           // 6144
__global__ void __launch_bounds__(256)
k0_count_cvtw(const int* __restrict__ tok,
              const float* __restrict__ s0, const float* __restrict__ s1,
              const float* __restrict__ s2, const float* __restrict__ s3)
{
    const int blk = blockIdx.x;
    if (blk < 64){
        int tid = threadIdx.x, wid = tid>>5, lane = tid&31;
        int r = route_of(tok[blk*256 + tid]);
        __shared__ int wcnt[8][8];
        unsigned m[8];
        #pragma unroll
        for (int e = 0; e < 8; e++) m[e] = __ballot_sync(0xffffffffu, r == e);
        if (lane < 8) wcnt[wid][lane] = __popc(m[lane]);
        __syncthreads();
        if (tid < 8){
            int s = 0;
            #pragma unroll
            for (int w = 0; w < 8; w++) s += wcnt[w][tid];
            g_tileCnt[blk][tid] = s;
        }
        return;
    }
    int p = (blk - 64)*256 + threadIdx.x;
    int j = p * 2;
    const float* src; __half* dst;
    if (j < W0Q){ src = s0; dst = g_Winh; }
    else if ((j -= W0Q) < W1Q){ src = s1; dst = g_Wsinh; }
    else if ((j -= W1Q) < W2Q){ src = s2; dst = g_Wsoh; }
    else { j -= W2Q; src = s3; dst = g_Woth; }
    #pragma unroll
    for (int q = 0; q < 2; q++){
        float4 v = reinterpret_cast<const float4*>(src)[j + q];
        reinterpret_cast<uint2*>(dst)[j + q] =
            make_uint2(h2bits(__floats2half2_rn(v.x, v.y)), h2bits(__floats2half2_rn(v.z, v.w)));
    }
}

// ---------------- kernel 1: place (each block recomputes prefix) ----------
__global__ void __launch_bounds__(256)
k1_place(const int* __restrict__ tok)
{
    const int blk = blockIdx.x, tid = threadIdx.x, wid = tid>>5, lane = tid&31;
    __shared__ int s_off[8];
    __shared__ int s_tot[8];
    __shared__ int s_base[8];
    __shared__ int wcnt[8][8];

    if (tid < 8){
        const int e = tid;
        int run = 0, off = 0;
        for (int t = 0; t < 64; t++){
            if (t == blk) off = run;
            run += g_tileCnt[t][e];
        }
        s_tot[e] = run;
        s_off[e] = off;
    }
    __syncthreads();
    if (tid < 8){
        int base = 0;
        for (int e = 0; e < tid; e++) base += s_tot[e];
        s_base[tid] = base;
        if (blk == 0){
            g_eBase[tid] = base;
            g_cnt[tid]   = s_tot[tid];
            for (int b = 0; b < 8; b++){
                int run = 0, off = 0, s = 0;
                for (int t = 0; t < 64; t++){
                    if (t == b*8) off = run;
                    run += g_tileCnt[t][tid];
                    if (t >= b*8 && t < b*8 + 8) s += g_tileCnt[t][tid];
                }
                g_beOff[b][tid] = base + off;
                g_beCnt[b][tid] = s;
            }
        }
    }

    const int t = blk*256 + tid;
    const int r = route_of(tok[t]);
    unsigned m[8];
    #pragma unroll
    for (int e = 0; e < 8; e++) m[e] = __ballot_sync(0xffffffffu, r == e);
    if (lane < 8) wcnt[wid][lane] = __popc(m[lane]);
    __syncthreads();
    int wbase = 0;
    for (int w = 0; w < wid; w++) wbase += wcnt[w][r];
    int rank = wbase + __popc(m[r] & ((1u << lane) - 1u));
    g_list[s_base[r] + s_off[r] + rank] = t;
}

// ---------------- kernel 2: x gather + fp16 round --------------------------
__global__ void __launch_bounds__(256)
cvt_x(const float* __restrict__ x){
    const int pos = blockIdx.x;
    const int i   = threadIdx.x;
    const int tok = g_list[pos];
    float4 v = reinterpret_cast<const float4*>(x)[(size_t)tok*256 + i];
    reinterpret_cast<uint2*>(g_xg)[(size_t)pos*256 + i] =
        make_uint2(h2bits(__floats2half2_rn(v.x, v.y)), h2bits(__floats2half2_rn(v.z, v.w)));
}

// ---------------- grouped GEMM: 128x128 tile, 3-stage cp.async (frozen r13)
#define SSTR   144
#define ATILE  (128*SSTR)         // 18432
#define STAGE  (2*ATILE)          // 36864 : A | B
#define GSMEM  (3*STAGE)          // 110592

template<int MODE>
__global__ void __launch_bounds__(256, 2)
gemm_mma(const __half* __restrict__ A,
         const __half* __restrict__ W0, const __half* __restrict__ W1,
         const float* __restrict__ dparam, float* __restrict__ outp, int K)
{
    const int e   = blockIdx.z;
    const int cnt = g_cnt[e];
    const int m0  = blockIdx.x * 128;
    if (m0 >= cnt) return;
    const int n0  = blockIdx.y * 128;
    const int posBase = g_eBase[e];

    const __half* W;
    int nloc;
    if (MODE == 0){
        if (n0 < 256){ W = W0 + (size_t)e * NST * K;   nloc = n0; }
        else         { W = W1 + (size_t)e * HID * K;   nloc = n0 - 256; }
    } else {
        W = W0 + (size_t)e * 1024 * K;  nloc = n0;
    }

    extern __shared__ __align__(16) char sm[];

    const int tid  = threadIdx.x;
    const int wid  = tid >> 5;
    const int lane = tid & 31;

    const int lrow = tid >> 1;
    const int lcol = (tid & 1) * 32;
    int am = m0 + lrow; if (am >= cnt) am = cnt - 1;
    const __half* ap = A + (size_t)(posBase + am)*K + lcol;
    const __half* bp = W + (size_t)(nloc + lrow)*K + lcol;
    const uint32_t sb = smem_u32(sm);
    const uint32_t aoff = sb + (uint32_t)(lrow*SSTR + lcol*2);
    const uint32_t boff = aoff + ATILE;

    const int wm = wid & 1, wn = wid >> 1;
    const uint32_t a_base = sb + (uint32_t)((wm*64 + (lane & 15))*SSTR + (lane >> 4)*16);
    const uint32_t b_base = sb + ATILE +
        (uint32_t)((wn*32 + (lane >> 4)*8 + (lane & 7))*SSTR + ((lane >> 3) & 1)*16);

    float acc[4][4][4];
    #pragma unroll
    for (int mi=0;mi<4;mi++)
        #pragma unroll
        for (int ni=0;ni<4;ni++)
            #pragma unroll
            for (int q=0;q<4;q++) acc[mi][ni][q]=0.f;

    const int NC = K >> 6;

    auto issue = [&](int c){
        const uint32_t st = (uint32_t)((c % 3) * STAGE);
        const int k0 = c << 6;
        #pragma unroll
        for (int q = 0; q < 4; q++){
            cpa16(aoff + st + q*16, ap + k0 + q*8);
            cpa16(boff + st + q*16, bp + k0 + q*8);
        }
    };

    issue(0); CP_COMMIT();
    issue(1); CP_COMMIT();

    for (int c = 0; c < NC; c++){
        CP_WAIT1();
        __syncthreads();
        if (c + 2 < NC) issue(c + 2);
        CP_COMMIT();

        const uint32_t ab = a_base + (c % 3)*STAGE;
        const uint32_t bb = b_base + (c % 3)*STAGE;
        #pragma unroll
        for (int ks = 0; ks < 4; ks++){
            uint32_t ah[4][4], bh[2][4];
            // B first: first mma consumes bh[0] — have it in flight earliest
            #pragma unroll
            for (int np = 0; np < 2; np++)
                ldsm_x4(bh[np], bb + np*16*SSTR + ks*32);
            #pragma unroll
            for (int mi = 0; mi < 4; mi++)
                ldsm_x4(ah[mi], ab + mi*16*SSTR + ks*32);
            #pragma unroll
            for (int mi = 0; mi < 4; mi++)
                #pragma unroll
                for (int ni = 0; ni < 4; ni++){
                    const int np = ni >> 1, h = (ni & 1)*2;
                    mma16816h(acc[mi][ni], ah[mi], bh[np][h], bh[np][h+1]);
                }
        }
    }

    const int sec = (MODE == 2) ? (n0 >> 8) : 0;
    #pragma unroll
    for (int mi = 0; mi < 4; mi++){
        const int rt0 = wm*64 + mi*16 + (lane >> 2);
        #pragma unroll
        for (int hf = 0; hf < 2; hf++){
            const int rt = rt0 + hf*8;
            const int m  = m0 + rt;
            if (m >= cnt) continue;
            const int pos = posBase + m;
            #pragma unroll
            for (int ni = 0; ni < 4; ni++){
                float v0 = acc[mi][ni][hf*2], v1 = acc[mi][ni][hf*2+1];
                const int col = n0 + wn*32 + (ni>>1)*16 + (ni&1)*8 + (lane&3)*2;
                if (MODE == 0){
                    if (col < 256){
                        *(float2*)(g_u + (size_t)pos*NST + col) = make_float2(v0, v1);
                    } else {
                        float s0 = v0*sigmoidf_(v0), s1 = v1*sigmoidf_(v1);
                        *reinterpret_cast<uint32_t*>(g_shh + (size_t)pos*HID + (col - 256)) =
                            h2bits(__floats2half2_rn(s0, s1));
                    }
                } else if (MODE == 2){
                    const int off = col & 255;
                    const size_t base = (size_t)pos*NST + off;
                    if (sec == 0){
                        *(float2*)(g_a + base) = make_float2(sigmoidf_(v0), sigmoidf_(v1));
                    } else if (sec == 1){
                        float2 u2 = *(const float2*)(g_u + base);
                        *(float2*)(g_bu + base) = make_float2(ftanh_(v0)*u2.x, ftanh_(v1)*u2.y);
                    } else if (sec == 2){
                        *(float2*)(g_c + base) = make_float2(ftanh_(v0), ftanh_(v1));
                    } else {
                        float2 u2 = *(const float2*)(g_u + base);
                        float2 d2 = *(const float2*)(dparam + e*NST + off);
                        *(float2*)(g_sk + base) =
                            make_float2(sigmoidf_(v0)*d2.x*u2.x, sigmoidf_(v1)*d2.y*u2.y);
                    }
                } else {
                    const int tok = g_list[pos];
                    *(float2*)(outp + (size_t)tok*DIM + col) = make_float2(v0, v1);
                }
            }
        }
    }
}

// ---------------- parallel scan: 8 segments per (b,e) chain ---------------
// h_i = a_i h_{i-1} + bu_i  ->  per segment: h_end = P*h_start + S
// scan1: per-segment (P,S).  scan2: fold predecessors, re-walk, emit y.
__global__ void __launch_bounds__(256)
scan_part1()
{
    const int b = blockIdx.x, e = blockIdx.y, seg = blockIdx.z, tid = threadIdx.x;
    const int pos0 = g_beOff[b][e];
    const int n    = g_beCnt[b][e];
    const int L    = (n + NSEG - 1) / NSEG;
    const int i0   = seg * L;
    const int i1   = (i0 + L < n) ? (i0 + L) : n;

    float P = 1.f, S = 0.f;
    for (int i = i0; i < i1; i++){
        size_t idx = ((size_t)(pos0 + i))*NST + tid;
        float a  = g_a [idx];
        float bu = g_bu[idx];
        P = a * P;
        S = fmaf(a, S, bu);
    }
    const size_t o = (((size_t)(b*NEXP + e))*NSEG + seg)*NST + tid;
    g_segP[o] = P;
    g_segS[o] = S;
}

__global__ void __launch_bounds__(256)
scan_part2()
{
    const int b = blockIdx.x, e = blockIdx.y, seg = blockIdx.z, tid = threadIdx.x;
    const int pos0 = g_beOff[b][e];
    const int n    = g_beCnt[b][e];
    const int L    = (n + NSEG - 1) / NSEG;
    const int i0   = seg * L;
    const int i1   = (i0 + L < n) ? (i0 + L) : n;

    // fold predecessor segment summaries -> entry state
    float h = 0.f;
    const size_t sb = ((size_t)(b*NEXP + e))*NSEG*NST + tid;
    for (int s = 0; s < seg; s++){
        float P = g_segP[sb + (size_t)s*NST];
        float S = g_segS[sb + (size_t)s*NST];
        h = fmaf(P, h, S);
    }

    for (int i = i0; i < i1; i++){
        size_t idx = ((size_t)(pos0 + i))*NST + tid;
        float a  = g_a [idx];
        float bu = g_bu[idx];
        float c  = g_c [idx];
        float sk = g_sk[idx];
        h = fmaf(a, h, bu);
        float y = fmaf(c, h, sk);
        g_yh[idx] = __float2half(y);
    }
}

// ---------------- launch ----------------
extern "C" void kernel_launch(void* const* d_in, const int* in_sizes, int n_in,
                              void* d_out, int out_size)
{
    const float* x     = (const float*)d_in[0];
    const int*   tok   = (const int*)  d_in[1];
    const float* Win   = (const float*)d_in[2];
    const float* Wsin  = (const float*)d_in[3];
    const float* Wsout = (const float*)d_in[4];
    const float* Wout  = (const float*)d_in[5];
    const float* dpar  = (const float*)d_in[6];
    float* outp = (float*)d_out;
    (void)in_sizes; (void)n_in; (void)out_size;

    cudaFuncSetAttribute(gemm_mma<0>, cudaFuncAttributeMaxDynamicSharedMemorySize, GSMEM);
    cudaFuncSetAttribute(gemm_mma<2>, cudaFuncAttributeMaxDynamicSharedMemorySize, GSMEM);
    cudaFuncSetAttribute(gemm_mma<3>, cudaFuncAttributeMaxDynamicSharedMemorySize, GSMEM);

    __half *xg, *shh, *yh, *winh, *wsih, *wsoh, *woth;
    cudaGetSymbolAddress((void**)&xg,   g_xg);
    cudaGetSymbolAddress((void**)&shh,  g_shh);
    cudaGetSymbolAddress((void**)&yh,   g_yh);
    cudaGetSymbolAddress((void**)&winh, g_Winh);
    cudaGetSymbolAddress((void**)&wsih, g_Wsinh);
    cudaGetSymbolAddress((void**)&wsoh, g_Wsoh);
    cudaGetSymbolAddress((void**)&woth, g_Woth);

    k0_count_cvtw<<<64 + CVT_BLKS, 256>>>(tok, Win, Wsin, Wsout, Wout);
    k1_place<<<64, 256>>>(tok);
    cvt_x<<<NTOK, 256>>>(x);

    dim3 blk(256);
    // fused u|sh GEMM, K=1024
    gemm_mma<0><<<dim3(20, 6, NEXP), blk, GSMEM>>>(xg,  winh, wsih, nullptr, nullptr, DIM);
    // gates = sh . Wsout^T (K=512)
    gemm_mma<2><<<dim3(20, 8, NEXP), blk, GSMEM>>>(shh, wsoh, nullptr, dpar,  nullptr, HID);
    // recurrence: parallel two-phase scan (8 segments per chain)
    scan_part1<<<dim3(BATCH, NEXP, NSEG), 256>>>();
    scan_part2<<<dim3(BATCH, NEXP, NSEG), 256>>>();
    // out = y . Wout^T (K=256)
    gemm_mma<3><<<dim3(20, 8, NEXP), blk, GSMEM>>>(yh,  woth, nullptr, nullptr, outp,  NST);
}

// round 17
// speedup vs baseline: 1.6293x; 1.0335x over previous
#include <cuda_runtime.h>
#include <cuda_fp16.h>
#include <cstdint>

#define BATCH 8
#define SEQ   2048
#define DIM   1024
#define NST   256
#define HID   512
#define NEXP  8
#define NTOK  (BATCH*SEQ)   // 16384
#define NSEG  16

// ---------------- device scratch (static, allocation-free) ----------------
__device__ __half g_xg[NTOK*DIM];
__device__ __half g_Winh [NEXP*NST*DIM];
__device__ __half g_Wsinh[NEXP*HID*DIM];
__device__ __half g_Wsoh [NEXP*4*NST*HID];
__device__ __half g_Woth [NEXP*DIM*NST];
__device__ __half g_shh[NTOK*HID];
__device__ __half g_yh [NTOK*NST];
__device__ float g_u [NTOK*NST];
__device__ float g_a [NTOK*NST], g_bu[NTOK*NST], g_c[NTOK*NST], g_sk[NTOK*NST];
__device__ float g_segP[BATCH*NEXP*NSEG*NST];
__device__ float g_segS[BATCH*NEXP*NSEG*NST];
__device__ int g_list[NTOK];
__device__ int g_tileCnt[64][NEXP];
__device__ int g_eBase[NEXP];
__device__ int g_cnt[NEXP];
__device__ int g_beOff[BATCH][NEXP];
__device__ int g_beCnt[BATCH][NEXP];

__device__ __forceinline__ float sigmoidf_(float x){ return 1.f/(1.f+__expf(-x)); }
__device__ __forceinline__ float ftanh_(float x){
    float e = __expf(2.f*x);
    return 1.f - __fdividef(2.f, e + 1.f);
}

__device__ __forceinline__ uint32_t smem_u32(const void* p){
    uint32_t a;
    asm("{ .reg .u64 t; cvta.to.shared.u64 t, %1; cvt.u32.u64 %0, t; }" : "=r"(a) : "l"(p));
    return a;
}
__device__ __forceinline__ void ldsm_x4(uint32_t* r, uint32_t addr){
    asm volatile("ldmatrix.sync.aligned.m8n8.x4.shared.b16 {%0,%1,%2,%3}, [%4];"
        : "=r"(r[0]),"=r"(r[1]),"=r"(r[2]),"=r"(r[3]) : "r"(addr));
}
__device__ __forceinline__ void mma16816h(float* d, const uint32_t* a, uint32_t b0, uint32_t b1){
    asm volatile("mma.sync.aligned.m16n8k16.row.col.f32.f16.f16.f32 "
        "{%0,%1,%2,%3}, {%4,%5,%6,%7}, {%8,%9}, {%0,%1,%2,%3};"
        : "+f"(d[0]),"+f"(d[1]),"+f"(d[2]),"+f"(d[3])
        : "r"(a[0]),"r"(a[1]),"r"(a[2]),"r"(a[3]), "r"(b0),"r"(b1));
}
__device__ __forceinline__ void cpa16(uint32_t dst, const void* src){
    asm volatile("cp.async.cg.shared.global [%0], [%1], 16;" :: "r"(dst), "l"(src));
}
#define CP_COMMIT() asm volatile("cp.async.commit_group;" ::: "memory")
#define CP_WAIT1()  asm volatile("cp.async.wait_group 1;"  ::: "memory")
__device__ __forceinline__ uint32_t h2bits(__half2 h){ return *reinterpret_cast<uint32_t*>(&h); }
__device__ __forceinline__ int route_of(int tokid){
    unsigned x = (unsigned)tokid;
    x ^= x >> 16; x *= 2246822507u;
    x ^= x >> 13; x *= 3266489909u;
    x ^= x >> 16;
    return (int)(x & 7u);
}

// ---------------- fused kernel 0: count (blocks 0..63) + weight cvt -------
#define W0Q (NEXP*NST*DIM/4)
#define W1Q (NEXP*HID*DIM/4)
#define W2Q (NEXP*4*NST*HID/4)
#define W3Q (NEXP*DIM*NST/4)
#define WTOTQ (W0Q+W1Q+W2Q+W3Q)
#define WPAIRS (WTOTQ/2)
#define CVT_BLKS (WPAIRS/256)           // 6144
__global__ void __launch_bounds__(256)
k0_count_cvtw(const int* __restrict__ tok,
              const float* __restrict__ s0, const float* __restrict__ s1,
              const float* __restrict__ s2, const float* __restrict__ s3)
{
    const int blk = blockIdx.x;
    if (blk < 64){
        int tid = threadIdx.x, wid = tid>>5, lane = tid&31;
        int r = route_of(tok[blk*256 + tid]);
        __shared__ int wcnt[8][8];
        unsigned m[8];
        #pragma unroll
        for (int e = 0; e < 8; e++) m[e] = __ballot_sync(0xffffffffu, r == e);
        if (lane < 8) wcnt[wid][lane] = __popc(m[lane]);
        __syncthreads();
        if (tid < 8){
            int s = 0;
            #pragma unroll
            for (int w = 0; w < 8; w++) s += wcnt[w][tid];
            g_tileCnt[blk][tid] = s;
        }
        return;
    }
    int p = (blk - 64)*256 + threadIdx.x;
    int j = p * 2;
    const float* src; __half* dst;
    if (j < W0Q){ src = s0; dst = g_Winh; }
    else if ((j -= W0Q) < W1Q){ src = s1; dst = g_Wsinh; }
    else if ((j -= W1Q) < W2Q){ src = s2; dst = g_Wsoh; }
    else { j -= W2Q; src = s3; dst = g_Woth; }
    #pragma unroll
    for (int q = 0; q < 2; q++){
        float4 v = reinterpret_cast<const float4*>(src)[j + q];
        reinterpret_cast<uint2*>(dst)[j + q] =
            make_uint2(h2bits(__floats2half2_rn(v.x, v.y)), h2bits(__floats2half2_rn(v.z, v.w)));
    }
}

// ---------------- kernel 1: place (each block recomputes prefix) ----------
__global__ void __launch_bounds__(256)
k1_place(const int* __restrict__ tok)
{
    const int blk = blockIdx.x, tid = threadIdx.x, wid = tid>>5, lane = tid&31;
    __shared__ int s_off[8];
    __shared__ int s_tot[8];
    __shared__ int s_base[8];
    __shared__ int wcnt[8][8];

    if (tid < 8){
        const int e = tid;
        int run = 0, off = 0;
        for (int t = 0; t < 64; t++){
            if (t == blk) off = run;
            run += g_tileCnt[t][e];
        }
        s_tot[e] = run;
        s_off[e] = off;
    }
    __syncthreads();
    if (tid < 8){
        int base = 0;
        for (int e = 0; e < tid; e++) base += s_tot[e];
        s_base[tid] = base;
        if (blk == 0){
            g_eBase[tid] = base;
            g_cnt[tid]   = s_tot[tid];
            for (int b = 0; b < 8; b++){
                int run = 0, off = 0, s = 0;
                for (int t = 0; t < 64; t++){
                    if (t == b*8) off = run;
                    run += g_tileCnt[t][tid];
                    if (t >= b*8 && t < b*8 + 8) s += g_tileCnt[t][tid];
                }
                g_beOff[b][tid] = base + off;
                g_beCnt[b][tid] = s;
            }
        }
    }

    const int t = blk*256 + tid;
    const int r = route_of(tok[t]);
    unsigned m[8];
    #pragma unroll
    for (int e = 0; e < 8; e++) m[e] = __ballot_sync(0xffffffffu, r == e);
    if (lane < 8) wcnt[wid][lane] = __popc(m[lane]);
    __syncthreads();
    int wbase = 0;
    for (int w = 0; w < wid; w++) wbase += wcnt[w][r];
    int rank = wbase + __popc(m[r] & ((1u << lane) - 1u));
    g_list[s_base[r] + s_off[r] + rank] = t;
}

// ---------------- kernel 2: x gather + fp16 round, 8 rows/block ------------
__global__ void __launch_bounds__(256)
cvt_x(const float* __restrict__ x){
    const int pos  = blockIdx.x * 8 + (threadIdx.x >> 5);   // 8 rows per block
    const int lane = threadIdx.x & 31;
    const int tok  = g_list[pos];
    const float4* src = reinterpret_cast<const float4*>(x) + (size_t)tok*256;
    uint2* dst = reinterpret_cast<uint2*>(g_xg) + (size_t)pos*256;
    #pragma unroll
    for (int q = 0; q < 8; q++){
        float4 v = src[lane + q*32];
        dst[lane + q*32] =
            make_uint2(h2bits(__floats2half2_rn(v.x, v.y)), h2bits(__floats2half2_rn(v.z, v.w)));
    }
}

// ---------------- grouped GEMM: 128x128 tile, 3-stage cp.async (frozen) ---
#define SSTR   144
#define ATILE  (128*SSTR)         // 18432
#define STAGE  (2*ATILE)          // 36864 : A | B
#define GSMEM  (3*STAGE)          // 110592

template<int MODE>
__global__ void __launch_bounds__(256, 2)
gemm_mma(const __half* __restrict__ A,
         const __half* __restrict__ W0, const __half* __restrict__ W1,
         const float* __restrict__ dparam, float* __restrict__ outp, int K)
{
    const int e   = blockIdx.z;
    const int cnt = g_cnt[e];
    const int m0  = blockIdx.x * 128;
    if (m0 >= cnt) return;
    const int n0  = blockIdx.y * 128;
    const int posBase = g_eBase[e];

    const __half* W;
    int nloc;
    if (MODE == 0){
        if (n0 < 256){ W = W0 + (size_t)e * NST * K;   nloc = n0; }
        else         { W = W1 + (size_t)e * HID * K;   nloc = n0 - 256; }
    } else {
        W = W0 + (size_t)e * 1024 * K;  nloc = n0;
    }

    extern __shared__ __align__(16) char sm[];

    const int tid  = threadIdx.x;
    const int wid  = tid >> 5;
    const int lane = tid & 31;

    const int lrow = tid >> 1;
    const int lcol = (tid & 1) * 32;
    int am = m0 + lrow; if (am >= cnt) am = cnt - 1;
    const __half* ap = A + (size_t)(posBase + am)*K + lcol;
    const __half* bp = W + (size_t)(nloc + lrow)*K + lcol;
    const uint32_t sb = smem_u32(sm);
    const uint32_t aoff = sb + (uint32_t)(lrow*SSTR + lcol*2);
    const uint32_t boff = aoff + ATILE;

    const int wm = wid & 1, wn = wid >> 1;
    const uint32_t a_base = sb + (uint32_t)((wm*64 + (lane & 15))*SSTR + (lane >> 4)*16);
    const uint32_t b_base = sb + ATILE +
        (uint32_t)((wn*32 + (lane >> 4)*8 + (lane & 7))*SSTR + ((lane >> 3) & 1)*16);

    float acc[4][4][4];
    #pragma unroll
    for (int mi=0;mi<4;mi++)
        #pragma unroll
        for (int ni=0;ni<4;ni++)
            #pragma unroll
            for (int q=0;q<4;q++) acc[mi][ni][q]=0.f;

    const int NC = K >> 6;

    auto issue = [&](int c){
        const uint32_t st = (uint32_t)((c % 3) * STAGE);
        const int k0 = c << 6;
        #pragma unroll
        for (int q = 0; q < 4; q++){
            cpa16(aoff + st + q*16, ap + k0 + q*8);
            cpa16(boff + st + q*16, bp + k0 + q*8);
        }
    };

    issue(0); CP_COMMIT();
    issue(1); CP_COMMIT();

    for (int c = 0; c < NC; c++){
        CP_WAIT1();
        __syncthreads();
        if (c + 2 < NC) issue(c + 2);
        CP_COMMIT();

        const uint32_t ab = a_base + (c % 3)*STAGE;
        const uint32_t bb = b_base + (c % 3)*STAGE;
        #pragma unroll
        for (int ks = 0; ks < 4; ks++){
            uint32_t ah[4][4], bh[2][4];
            #pragma unroll
            for (int np = 0; np < 2; np++)
                ldsm_x4(bh[np], bb + np*16*SSTR + ks*32);
            #pragma unroll
            for (int mi = 0; mi < 4; mi++)
                ldsm_x4(ah[mi], ab + mi*16*SSTR + ks*32);
            #pragma unroll
            for (int mi = 0; mi < 4; mi++)
                #pragma unroll
                for (int ni = 0; ni < 4; ni++){
                    const int np = ni >> 1, h = (ni & 1)*2;
                    mma16816h(acc[mi][ni], ah[mi], bh[np][h], bh[np][h+1]);
                }
        }
    }

    const int sec = (MODE == 2) ? (n0 >> 8) : 0;
    #pragma unroll
    for (int mi = 0; mi < 4; mi++){
        const int rt0 = wm*64 + mi*16 + (lane >> 2);
        #pragma unroll
        for (int hf = 0; hf < 2; hf++){
            const int rt = rt0 + hf*8;
            const int m  = m0 + rt;
            if (m >= cnt) continue;
            const int pos = posBase + m;
            #pragma unroll
            for (int ni = 0; ni < 4; ni++){
                float v0 = acc[mi][ni][hf*2], v1 = acc[mi][ni][hf*2+1];
                const int col = n0 + wn*32 + (ni>>1)*16 + (ni&1)*8 + (lane&3)*2;
                if (MODE == 0){
                    if (col < 256){
                        *(float2*)(g_u + (size_t)pos*NST + col) = make_float2(v0, v1);
                    } else {
                        float s0 = v0*sigmoidf_(v0), s1 = v1*sigmoidf_(v1);
                        *reinterpret_cast<uint32_t*>(g_shh + (size_t)pos*HID + (col - 256)) =
                            h2bits(__floats2half2_rn(s0, s1));
                    }
                } else if (MODE == 2){
                    const int off = col & 255;
                    const size_t base = (size_t)pos*NST + off;
                    if (sec == 0){
                        *(float2*)(g_a + base) = make_float2(sigmoidf_(v0), sigmoidf_(v1));
                    } else if (sec == 1){
                        float2 u2 = *(const float2*)(g_u + base);
                        *(float2*)(g_bu + base) = make_float2(ftanh_(v0)*u2.x, ftanh_(v1)*u2.y);
                    } else if (sec == 2){
                        *(float2*)(g_c + base) = make_float2(ftanh_(v0), ftanh_(v1));
                    } else {
                        float2 u2 = *(const float2*)(g_u + base);
                        float2 d2 = *(const float2*)(dparam + e*NST + off);
                        *(float2*)(g_sk + base) =
                            make_float2(sigmoidf_(v0)*d2.x*u2.x, sigmoidf_(v1)*d2.y*u2.y);
                    }
                } else {
                    const int tok = g_list[pos];
                    *(float2*)(outp + (size_t)tok*DIM + col) = make_float2(v0, v1);
                }
            }
        }
    }
}

// ---------------- parallel scan: 16 segments per (b,e) chain --------------
__global__ void __launch_bounds__(256)
scan_part1()
{
    const int b = blockIdx.x, e = blockIdx.y, seg = blockIdx.z, tid = threadIdx.x;
    const int pos0 = g_beOff[b][e];
    const int n    = g_beCnt[b][e];
    const int L    = (n + NSEG - 1) / NSEG;
    const int i0   = seg * L;
    const int i1   = (i0 + L < n) ? (i0 + L) : n;

    float P = 1.f, S = 0.f;
    for (int i = i0; i < i1; i++){
        size_t idx = ((size_t)(pos0 + i))*NST + tid;
        float a  = g_a [idx];
        float bu = g_bu[idx];
        P = a * P;
        S = fmaf(a, S, bu);
    }
    const size_t o = (((size_t)(b*NEXP + e))*NSEG + seg)*NST + tid;
    g_segP[o] = P;
    g_segS[o] = S;
}

__global__ void __launch_bounds__(256)
scan_part2()
{
    const int b = blockIdx.x, e = blockIdx.y, seg = blockIdx.z, tid = threadIdx.x;
    const int pos0 = g_beOff[b][e];
    const int n    = g_beCnt[b][e];
    const int L    = (n + NSEG - 1) / NSEG;
    const int i0   = seg * L;
    const int i1   = (i0 + L < n) ? (i0 + L) : n;

    float h = 0.f;
    const size_t sb = ((size_t)(b*NEXP + e))*NSEG*NST + tid;
    for (int s = 0; s < seg; s++){
        float P = g_segP[sb + (size_t)s*NST];
        float S = g_segS[sb + (size_t)s*NST];
        h = fmaf(P, h, S);
    }

    for (int i = i0; i < i1; i++){
        size_t idx = ((size_t)(pos0 + i))*NST + tid;
        float a  = g_a [idx];
        float bu = g_bu[idx];
        float c  = g_c [idx];
        float sk = g_sk[idx];
        h = fmaf(a, h, bu);
        float y = fmaf(c, h, sk);
        g_yh[idx] = __float2half(y);
    }
}

// ---------------- launch ----------------
extern "C" void kernel_launch(void* const* d_in, const int* in_sizes, int n_in,
                              void* d_out, int out_size)
{
    const float* x     = (const float*)d_in[0];
    const int*   tok   = (const int*)  d_in[1];
    const float* Win   = (const float*)d_in[2];
    const float* Wsin  = (const float*)d_in[3];
    const float* Wsout = (const float*)d_in[4];
    const float* Wout  = (const float*)d_in[5];
    const float* dpar  = (const float*)d_in[6];
    float* outp = (float*)d_out;
    (void)in_sizes; (void)n_in; (void)out_size;

    cudaFuncSetAttribute(gemm_mma<0>, cudaFuncAttributeMaxDynamicSharedMemorySize, GSMEM);
    cudaFuncSetAttribute(gemm_mma<2>, cudaFuncAttributeMaxDynamicSharedMemorySize, GSMEM);
    cudaFuncSetAttribute(gemm_mma<3>, cudaFuncAttributeMaxDynamicSharedMemorySize, GSMEM);

    __half *xg, *shh, *yh, *winh, *wsih, *wsoh, *woth;
    cudaGetSymbolAddress((void**)&xg,   g_xg);
    cudaGetSymbolAddress((void**)&shh,  g_shh);
    cudaGetSymbolAddress((void**)&yh,   g_yh);
    cudaGetSymbolAddress((void**)&winh, g_Winh);
    cudaGetSymbolAddress((void**)&wsih, g_Wsinh);
    cudaGetSymbolAddress((void**)&wsoh, g_Wsoh);
    cudaGetSymbolAddress((void**)&woth, g_Woth);

    k0_count_cvtw<<<64 + CVT_BLKS, 256>>>(tok, Win, Wsin, Wsout, Wout);
    k1_place<<<64, 256>>>(tok);
    cvt_x<<<NTOK/8, 256>>>(x);

    dim3 blk(256);
    // fused u|sh GEMM, K=1024
    gemm_mma<0><<<dim3(20, 6, NEXP), blk, GSMEM>>>(xg,  winh, wsih, nullptr, nullptr, DIM);
    // gates = sh . Wsout^T (K=512)
    gemm_mma<2><<<dim3(20, 8, NEXP), blk, GSMEM>>>(shh, wsoh, nullptr, dpar,  nullptr, HID);
    // recurrence: parallel two-phase scan (16 segments per chain)
    scan_part1<<<dim3(BATCH, NEXP, NSEG), 256>>>();
    scan_part2<<<dim3(BATCH, NEXP, NSEG), 256>>>();
    // out = y . Wout^T (K=256)
    gemm_mma<3><<<dim3(20, 8, NEXP), blk, GSMEM>>>(yh,  woth, nullptr, nullptr, outp,  NST);
}